// round 4
// baseline (speedup 1.0000x reference)
#include <cuda_runtime.h>
#include <cuda_bf16.h>
#include <cstdint>

#define N_NODES 50000
#define N_EDGES 1600000
#define C 128
#define E_TOT (N_EDGES + N_NODES)
#define NEG_SLOPE 0.2f
#define ENC_NEG_INF ((int)0x80000000)

// -------- scratch (no device allocs allowed) --------
__device__ float g_h[(size_t)N_NODES * C];   // h = x @ W
__device__ float g_es[N_NODES];              // h . a_src
__device__ float g_ed[N_NODES];              // h . a_dst
__device__ int   g_m[N_NODES];               // encoded segment max
__device__ float g_denom[N_NODES];           // segment sum of exp

__device__ __forceinline__ int enc_f(float f) {
    int i = __float_as_int(f);
    return i < 0 ? (i ^ 0x7FFFFFFF) : i;
}
__device__ __forceinline__ float dec_f(int i) {
    return __int_as_float(i < 0 ? (i ^ 0x7FFFFFFF) : i);
}
__device__ __forceinline__ float lrelu(float x) {
    return x > 0.f ? x : NEG_SLOPE * x;
}

// K1: h = x @ W  (+ fused e_src, e_dst). One node per 128-thread block.
__global__ void k_gemm1(const float* __restrict__ x, const float* __restrict__ W,
                        const float* __restrict__ a_src, const float* __restrict__ a_dst) {
    int n = blockIdx.x;
    int c = threadIdx.x;
    __shared__ float xs[C];
    __shared__ float rs[4], rd[4];
    xs[c] = x[(size_t)n * C + c];
    __syncthreads();
    float acc = 0.f;
#pragma unroll 16
    for (int k = 0; k < C; k++)
        acc = fmaf(xs[k], W[k * C + c], acc);
    g_h[(size_t)n * C + c] = acc;

    float ps = acc * a_src[c];
    float pd = acc * a_dst[c];
#pragma unroll
    for (int o = 16; o > 0; o >>= 1) {
        ps += __shfl_down_sync(0xffffffffu, ps, o);
        pd += __shfl_down_sync(0xffffffffu, pd, o);
    }
    if ((c & 31) == 0) { rs[c >> 5] = ps; rd[c >> 5] = pd; }
    __syncthreads();
    if (c == 0) {
        g_es[n] = rs[0] + rs[1] + rs[2] + rs[3];
        g_ed[n] = rd[0] + rd[1] + rd[2] + rd[3];
    }
}

// K2: init accumulators. zacc lives in d_out's z region.
__global__ void k_init(float* __restrict__ zacc) {
    size_t i = (size_t)blockIdx.x * blockDim.x + threadIdx.x;
    size_t total = (size_t)N_NODES * C;
    size_t stride = (size_t)gridDim.x * blockDim.x;
    for (size_t j = i; j < total; j += stride)
        zacc[j] = 0.f;
    for (size_t j = i; j < N_NODES; j += stride) {
        g_m[j] = ENC_NEG_INF;
        g_denom[j] = 0.f;
    }
}

// K3: segment max via atomicMax on order-preserving int encoding.
// edge_index is int32 (JAX x64 disabled: "int64" arrays are actually int32).
__global__ void k_segmax(const int* __restrict__ ei) {
    int e = blockIdx.x * blockDim.x + threadIdx.x;
    if (e >= E_TOT) return;
    int s, d;
    if (e < N_EDGES) { s = ei[e]; d = ei[N_EDGES + e]; }
    else             { s = e - N_EDGES; d = s; }
    float l = lrelu(g_es[s] + g_ed[d]);
    atomicMax(&g_m[d], enc_f(l));
}

// K4: denom = segment_sum(exp(logit - m[dst]))
__global__ void k_denom(const int* __restrict__ ei) {
    int e = blockIdx.x * blockDim.x + threadIdx.x;
    if (e >= E_TOT) return;
    int s, d;
    if (e < N_EDGES) { s = ei[e]; d = ei[N_EDGES + e]; }
    else             { s = e - N_EDGES; d = s; }
    float l = lrelu(g_es[s] + g_ed[d]);
    float mf = dec_f(g_m[d]);
    atomicAdd(&g_denom[d], __expf(l - mf));
}

// K5: weighted scatter z[dst] += coef * h[src]. One warp per edge.
__global__ void k_scatter(const int* __restrict__ ei, float* __restrict__ zacc) {
    int gt = blockIdx.x * blockDim.x + threadIdx.x;
    int e = gt >> 5;
    int lane = threadIdx.x & 31;
    if (e >= E_TOT) return;
    int s = 0, d = 0;
    float coef = 0.f;
    if (lane == 0) {
        if (e < N_EDGES) { s = ei[e]; d = ei[N_EDGES + e]; }
        else             { s = e - N_EDGES; d = s; }
        float l = lrelu(g_es[s] + g_ed[d]);
        float mf = dec_f(g_m[d]);
        coef = __expf(l - mf) / g_denom[d];
    }
    coef = __shfl_sync(0xffffffffu, coef, 0);
    s    = __shfl_sync(0xffffffffu, s, 0);
    d    = __shfl_sync(0xffffffffu, d, 0);

    const float4* hr = (const float4*)(g_h + (size_t)s * C);
    float4 v = hr[lane];
    float* zr = zacc + (size_t)d * C + lane * 4;
    atomicAdd(zr + 0, coef * v.x);
    atomicAdd(zr + 1, coef * v.y);
    atomicAdd(zr + 2, coef * v.z);
    atomicAdd(zr + 3, coef * v.w);
}

// K6: finalize z (+bias) and recon = tanh(z @ Wd + bd).
__global__ void k_decode(const float* __restrict__ b_gat, const float* __restrict__ Wd,
                         const float* __restrict__ bd, float* __restrict__ out) {
    int n = blockIdx.x;
    int c = threadIdx.x;
    __shared__ float zs[C];
    float* zrow = out + (size_t)N_NODES * C + (size_t)n * C;
    float zc = zrow[c] + b_gat[c];
    zs[c] = zc;
    zrow[c] = zc;                 // final z output
    __syncthreads();
    float acc = bd[c];
#pragma unroll 16
    for (int k = 0; k < C; k++)
        acc = fmaf(zs[k], Wd[k * C + c], acc);
    out[(size_t)n * C + c] = tanhf(acc);   // recon output
}

extern "C" void kernel_launch(void* const* d_in, const int* in_sizes, int n_in,
                              void* d_out, int out_size) {
    const float* x     = (const float*)d_in[0];
    const int*   ei    = (const int*)d_in[1];     // int32! (JAX x64 off)
    const float* W     = (const float*)d_in[2];
    const float* a_src = (const float*)d_in[3];
    const float* a_dst = (const float*)d_in[4];
    const float* b_gat = (const float*)d_in[5];
    const float* Wd    = (const float*)d_in[6];
    const float* bd    = (const float*)d_in[7];
    float* out  = (float*)d_out;
    float* zacc = out + (size_t)N_NODES * C;   // z region doubles as accumulator

    k_gemm1<<<N_NODES, C>>>(x, W, a_src, a_dst);
    k_init<<<1024, 256>>>(zacc);
    {
        int threads = 256;
        int blocks = (E_TOT + threads - 1) / threads;
        k_segmax<<<blocks, threads>>>(ei);
        k_denom<<<blocks, threads>>>(ei);
    }
    {
        long long tot = (long long)E_TOT * 32;
        int threads = 256;
        int blocks = (int)((tot + threads - 1) / threads);
        k_scatter<<<blocks, threads>>>(ei, zacc);
    }
    k_decode<<<N_NODES, C>>>(b_gat, Wd, bd, out);
}

// round 5
// speedup vs baseline: 1.6267x; 1.6267x over previous
#include <cuda_runtime.h>
#include <cuda_bf16.h>
#include <cstdint>

#define N_NODES 50000
#define N_EDGES 1600000
#define C 128
#define E_TOT (N_EDGES + N_NODES)
#define NEG_SLOPE 0.2f
#define NEG_INF (-1e30f)

// -------- scratch (no device allocs allowed) --------
__device__ float g_h[(size_t)N_NODES * C];   // h = x @ W
__device__ float g_es[N_NODES];              // h . a_src
__device__ float g_ed[N_NODES];              // h . a_dst
__device__ int   g_deg[N_NODES];             // in-degree histogram
__device__ int   g_off[N_NODES + 1];         // CSR offsets
__device__ int   g_cursor[N_NODES];          // fill cursors
__device__ int   g_adj[E_TOT];               // src ids bucketed by dst

__device__ __forceinline__ float lrelu(float x) {
    return x > 0.f ? x : NEG_SLOPE * x;
}

// K1: h = x @ W  (+ fused e_src, e_dst). One node per 128-thread block.
__global__ void k_gemm1(const float* __restrict__ x, const float* __restrict__ W,
                        const float* __restrict__ a_src, const float* __restrict__ a_dst) {
    int n = blockIdx.x;
    int c = threadIdx.x;
    __shared__ float xs[C];
    __shared__ float rs[4], rd[4];
    xs[c] = x[(size_t)n * C + c];
    __syncthreads();
    float acc = 0.f;
#pragma unroll 16
    for (int k = 0; k < C; k++)
        acc = fmaf(xs[k], W[k * C + c], acc);
    g_h[(size_t)n * C + c] = acc;

    float ps = acc * a_src[c];
    float pd = acc * a_dst[c];
#pragma unroll
    for (int o = 16; o > 0; o >>= 1) {
        ps += __shfl_down_sync(0xffffffffu, ps, o);
        pd += __shfl_down_sync(0xffffffffu, pd, o);
    }
    if ((c & 31) == 0) { rs[c >> 5] = ps; rd[c >> 5] = pd; }
    __syncthreads();
    if (c == 0) {
        g_es[n] = rs[0] + rs[1] + rs[2] + rs[3];
        g_ed[n] = rd[0] + rd[1] + rd[2] + rd[3];
    }
}

// zero in-degree histogram
__global__ void k_zero() {
    int i = blockIdx.x * blockDim.x + threadIdx.x;
    if (i < N_NODES) g_deg[i] = 0;
}

// histogram of destinations (self-loops included)
__global__ void k_hist(const int* __restrict__ ei) {
    int e = blockIdx.x * blockDim.x + threadIdx.x;
    if (e >= E_TOT) return;
    int d = (e < N_EDGES) ? ei[N_EDGES + e] : (e - N_EDGES);
    atomicAdd(&g_deg[d], 1);
}

// single-block exclusive scan -> g_off (and g_cursor copy)
__global__ void k_scan() {
    __shared__ int sbuf[1024];
    __shared__ int s_carry;
    int tid = threadIdx.x;
    if (tid == 0) s_carry = 0;
    __syncthreads();
    for (int base = 0; base <= N_NODES; base += 1024) {
        int idx = base + tid;
        int v = (idx < N_NODES) ? g_deg[idx] : 0;
        // Hillis-Steele inclusive scan in smem
        sbuf[tid] = v;
        __syncthreads();
        int val = v;
#pragma unroll
        for (int o = 1; o < 1024; o <<= 1) {
            int t = (tid >= o) ? sbuf[tid - o] : 0;
            __syncthreads();
            val += t;
            sbuf[tid] = val;
            __syncthreads();
        }
        int excl = s_carry + val - v;
        if (idx <= N_NODES) {
            g_off[idx] = excl;
            if (idx < N_NODES) g_cursor[idx] = excl;
        }
        __syncthreads();
        if (tid == 1023) s_carry += val;
        __syncthreads();
    }
}

// bucket src ids by dst
__global__ void k_fill(const int* __restrict__ ei) {
    int e = blockIdx.x * blockDim.x + threadIdx.x;
    if (e >= E_TOT) return;
    int s, d;
    if (e < N_EDGES) { s = ei[e]; d = ei[N_EDGES + e]; }
    else             { s = e - N_EDGES; d = s; }
    int pos = atomicAdd(&g_cursor[d], 1);
    g_adj[pos] = s;
}

// Fused per-node softmax + aggregation. One 128-thread block per dst node.
// No float atomics anywhere.
__global__ void k_gather(const float* __restrict__ b_gat, float* __restrict__ zout) {
    int n = blockIdx.x;
    int c = threadIdx.x;
    int off = g_off[n];
    int deg = g_off[n + 1] - off;
    float edn = g_ed[n];

    // ---- online (max, sum) over this node's in-edges ----
    float mt = NEG_INF, st = 0.f;
    for (int j = c; j < deg; j += C) {
        int s = g_adj[off + j];
        float l = lrelu(g_es[s] + edn);
        if (l > mt) { st *= __expf(mt - l); mt = l; }
        st += __expf(l - mt);
    }
    // warp merge
#pragma unroll
    for (int o = 16; o > 0; o >>= 1) {
        float mo = __shfl_down_sync(0xffffffffu, mt, o);
        float so = __shfl_down_sync(0xffffffffu, st, o);
        float pm = fmaxf(mt, mo);
        float a  = (mt > NEG_INF) ? st * __expf(mt - pm) : 0.f;
        float b  = (mo > NEG_INF) ? so * __expf(mo - pm) : 0.f;
        mt = pm; st = a + b;
    }
    __shared__ float sm[4], ss[4];
    __shared__ float bm, bs;
    if ((c & 31) == 0) { sm[c >> 5] = mt; ss[c >> 5] = st; }
    __syncthreads();
    if (c == 0) {
        float m0 = sm[0], s0 = ss[0];
#pragma unroll
        for (int w = 1; w < 4; w++) {
            float pm = fmaxf(m0, sm[w]);
            float a  = (m0 > NEG_INF)    ? s0 * __expf(m0 - pm)    : 0.f;
            float b  = (sm[w] > NEG_INF) ? ss[w] * __expf(sm[w] - pm) : 0.f;
            m0 = pm; s0 = a + b;
        }
        bm = m0; bs = s0;
    }
    __syncthreads();
    float m = bm;
    float inv_denom = 1.f / bs;

    // ---- weighted accumulation, chunked through smem ----
    __shared__ int   s_adj[C];
    __shared__ float s_coef[C];
    float acc = 0.f;
    for (int base = 0; base < deg; base += C) {
        int j = base + c;
        __syncthreads();
        if (j < deg) {
            int s = g_adj[off + j];
            s_adj[c]  = s;
            s_coef[c] = __expf(lrelu(g_es[s] + edn) - m);
        }
        __syncthreads();
        int lim = min(C, deg - base);
#pragma unroll 4
        for (int jj = 0; jj < lim; jj++)
            acc = fmaf(s_coef[jj], g_h[(size_t)s_adj[jj] * C + c], acc);
    }
    zout[(size_t)n * C + c] = acc * inv_denom + b_gat[c];
}

// decode: recon = tanh(z @ Wd + bd). z already finalized (bias included).
__global__ void k_decode(const float* __restrict__ Wd, const float* __restrict__ bd,
                         float* __restrict__ out) {
    int n = blockIdx.x;
    int c = threadIdx.x;
    __shared__ float zs[C];
    const float* zrow = out + (size_t)N_NODES * C + (size_t)n * C;
    zs[c] = zrow[c];
    __syncthreads();
    float acc = bd[c];
#pragma unroll 16
    for (int k = 0; k < C; k++)
        acc = fmaf(zs[k], Wd[k * C + c], acc);
    out[(size_t)n * C + c] = tanhf(acc);
}

extern "C" void kernel_launch(void* const* d_in, const int* in_sizes, int n_in,
                              void* d_out, int out_size) {
    const float* x     = (const float*)d_in[0];
    const int*   ei    = (const int*)d_in[1];     // int32 (JAX x64 off)
    const float* W     = (const float*)d_in[2];
    const float* a_src = (const float*)d_in[3];
    const float* a_dst = (const float*)d_in[4];
    const float* b_gat = (const float*)d_in[5];
    const float* Wd    = (const float*)d_in[6];
    const float* bd    = (const float*)d_in[7];
    float* out  = (float*)d_out;
    float* zout = out + (size_t)N_NODES * C;

    int threads = 256;
    int eblocks = (E_TOT + threads - 1) / threads;

    k_zero<<<(N_NODES + 255) / 256, 256>>>();
    k_gemm1<<<N_NODES, C>>>(x, W, a_src, a_dst);
    k_hist<<<eblocks, threads>>>(ei);
    k_scan<<<1, 1024>>>();
    k_fill<<<eblocks, threads>>>(ei);
    k_gather<<<N_NODES, C>>>(b_gat, zout);
    k_decode<<<N_NODES, C>>>(Wd, bd, out);
}

// round 6
// speedup vs baseline: 3.1925x; 1.9625x over previous
#include <cuda_runtime.h>
#include <cuda_bf16.h>
#include <cstdint>

#define N_NODES 50000
#define N_EDGES 1600000
#define C 128
#define E_TOT (N_EDGES + N_NODES)
#define NEG_SLOPE 0.2f
#define NEG_INF (-1e30f)
#define NBLK 49            // ceil(50000/1024)
#define NB 8               // nodes per block in GEMMs (50000 % 8 == 0)

// -------- scratch (no device allocs allowed) --------
__device__ float g_h[(size_t)N_NODES * C];
__device__ float g_es[N_NODES];
__device__ float g_ed[N_NODES];
__device__ int   g_deg[N_NODES];
__device__ int   g_off[N_NODES + 1];
__device__ int   g_cursor[N_NODES];
__device__ int   g_adj[E_TOT];
__device__ int   g_bsum[NBLK + 1];

__device__ __forceinline__ float lrelu(float x) {
    return x > 0.f ? x : NEG_SLOPE * x;
}

// ---- K1: h = x@W (+e_src,e_dst), 8 nodes per 128-thread block ----
__global__ void k_gemm1(const float* __restrict__ x, const float* __restrict__ W,
                        const float* __restrict__ a_src, const float* __restrict__ a_dst) {
    int nb = blockIdx.x * NB;
    int c = threadIdx.x;
    __shared__ float xs[NB][C];
#pragma unroll
    for (int i = 0; i < NB; i++)
        xs[i][c] = x[(size_t)(nb + i) * C + c];
    __syncthreads();
    float acc[NB];
#pragma unroll
    for (int i = 0; i < NB; i++) acc[i] = 0.f;
#pragma unroll 4
    for (int k = 0; k < C; k++) {
        float w = W[k * C + c];
#pragma unroll
        for (int i = 0; i < NB; i++)
            acc[i] = fmaf(xs[i][k], w, acc[i]);
    }
#pragma unroll
    for (int i = 0; i < NB; i++)
        g_h[(size_t)(nb + i) * C + c] = acc[i];

    // per-node dot products with a_src / a_dst
    float as = a_src[c], ad = a_dst[c];
    __shared__ float rs[NB][4], rd[NB][4];
    int lane = c & 31, wp = c >> 5;
#pragma unroll
    for (int i = 0; i < NB; i++) {
        float ps = acc[i] * as;
        float pd = acc[i] * ad;
#pragma unroll
        for (int o = 16; o > 0; o >>= 1) {
            ps += __shfl_down_sync(0xffffffffu, ps, o);
            pd += __shfl_down_sync(0xffffffffu, pd, o);
        }
        if (lane == 0) { rs[i][wp] = ps; rd[i][wp] = pd; }
    }
    __syncthreads();
    if (c < NB) {
        g_es[nb + c] = rs[c][0] + rs[c][1] + rs[c][2] + rs[c][3];
        g_ed[nb + c] = rd[c][0] + rd[c][1] + rd[c][2] + rd[c][3];
    }
}

__global__ void k_zero() {
    int i = blockIdx.x * blockDim.x + threadIdx.x;
    if (i < N_NODES) g_deg[i] = 0;
}

__global__ void k_hist(const int* __restrict__ ei) {
    int e = blockIdx.x * blockDim.x + threadIdx.x;
    if (e >= E_TOT) return;
    int d = (e < N_EDGES) ? ei[N_EDGES + e] : (e - N_EDGES);
    atomicAdd(&g_deg[d], 1);
}

// ---- scan phase 1: per-block exclusive scan + block sums ----
__global__ void k_scan1() {
    int b = blockIdx.x, tid = threadIdx.x;
    int idx = b * 1024 + tid;
    int v = (idx < N_NODES) ? g_deg[idx] : 0;
    int lane = tid & 31, wp = tid >> 5;
    int val = v;
#pragma unroll
    for (int o = 1; o < 32; o <<= 1) {
        int t = __shfl_up_sync(0xffffffffu, val, o);
        if (lane >= o) val += t;
    }
    __shared__ int wsum[32];
    if (lane == 31) wsum[wp] = val;
    __syncthreads();
    if (wp == 0) {
        int s = wsum[lane];
#pragma unroll
        for (int o = 1; o < 32; o <<= 1) {
            int t = __shfl_up_sync(0xffffffffu, s, o);
            if (lane >= o) s += t;
        }
        wsum[lane] = s;
    }
    __syncthreads();
    int incl = val + (wp ? wsum[wp - 1] : 0);
    if (idx < N_NODES) g_off[idx] = incl - v;        // local exclusive
    if (tid == 1023) g_bsum[b] = incl;               // block total
}

// ---- scan phase 2: scan the 49 block sums (tiny) ----
__global__ void k_scan2() {
    __shared__ int s[64];
    int tid = threadIdx.x;
    s[tid] = (tid < NBLK) ? g_bsum[tid] : 0;
    __syncthreads();
    if (tid == 0) {
        int acc = 0;
        for (int i = 0; i < NBLK; i++) { int t = s[i]; s[i] = acc; acc += t; }
        s[NBLK] = acc;
    }
    __syncthreads();
    if (tid <= NBLK) g_bsum[tid] = s[tid];
}

// ---- scan phase 3: add carries, publish cursors ----
__global__ void k_scan3() {
    int b = blockIdx.x, tid = threadIdx.x;
    int idx = b * 1024 + tid;
    if (idx < N_NODES) {
        int o = g_off[idx] + g_bsum[b];
        g_off[idx] = o;
        g_cursor[idx] = o;
    }
    if (idx == 0) g_off[N_NODES] = g_bsum[NBLK];
}

__global__ void k_fill(const int* __restrict__ ei) {
    int e = blockIdx.x * blockDim.x + threadIdx.x;
    if (e >= E_TOT) return;
    int s, d;
    if (e < N_EDGES) { s = ei[e]; d = ei[N_EDGES + e]; }
    else             { s = e - N_EDGES; d = s; }
    int pos = atomicAdd(&g_cursor[d], 1);
    g_adj[pos] = s;
}

// ---- fused softmax + aggregation: 1 warp per node, float4 lanes ----
__global__ void k_gather(const float* __restrict__ b_gat, float* __restrict__ zout) {
    int wp = threadIdx.x >> 5, lane = threadIdx.x & 31;
    int n = blockIdx.x * 4 + wp;          // 12500 * 4 == 50000, always valid
    int off = g_off[n];
    int deg = g_off[n + 1] - off;
    float edn = g_ed[n];

    // online (max, sum) across lanes
    float mt = NEG_INF, st = 0.f;
    for (int j = lane; j < deg; j += 32) {
        float l = lrelu(g_es[g_adj[off + j]] + edn);
        if (l > mt) { st *= __expf(mt - l); mt = l; }
        st += __expf(l - mt);
    }
#pragma unroll
    for (int o = 16; o > 0; o >>= 1) {
        float mo = __shfl_xor_sync(0xffffffffu, mt, o);
        float so = __shfl_xor_sync(0xffffffffu, st, o);
        float pm = fmaxf(mt, mo);
        float a = (mt > NEG_INF) ? st * __expf(mt - pm) : 0.f;
        float b = (mo > NEG_INF) ? so * __expf(mo - pm) : 0.f;
        mt = pm; st = a + b;
    }
    float inv = 1.f / st;                 // identical on all lanes

    // weighted accumulation: lane owns channels [4*lane, 4*lane+4)
    float4 acc = make_float4(0.f, 0.f, 0.f, 0.f);
    for (int base = 0; base < deg; base += 32) {
        int j = base + lane;
        int sj = 0; float cj = 0.f;
        if (j < deg) {
            sj = g_adj[off + j];
            cj = __expf(lrelu(g_es[sj] + edn) - mt);
        }
        int lim = min(32, deg - base);
        for (int it = 0; it < lim; it++) {
            int s    = __shfl_sync(0xffffffffu, sj, it);
            float cf = __shfl_sync(0xffffffffu, cj, it);
            float4 v = *(const float4*)(g_h + (size_t)s * C + lane * 4);
            acc.x = fmaf(cf, v.x, acc.x);
            acc.y = fmaf(cf, v.y, acc.y);
            acc.z = fmaf(cf, v.z, acc.z);
            acc.w = fmaf(cf, v.w, acc.w);
        }
    }
    float4 bg = *(const float4*)(b_gat + lane * 4);
    float4 o4 = make_float4(acc.x * inv + bg.x, acc.y * inv + bg.y,
                            acc.z * inv + bg.z, acc.w * inv + bg.w);
    *(float4*)(zout + (size_t)n * C + lane * 4) = o4;
}

// ---- decode: recon = tanh(z @ Wd + bd), 8 nodes per block ----
__global__ void k_decode(const float* __restrict__ Wd, const float* __restrict__ bd,
                         float* __restrict__ out) {
    int nb = blockIdx.x * NB;
    int c = threadIdx.x;
    __shared__ float zs[NB][C];
    const float* zbase = out + (size_t)N_NODES * C;
#pragma unroll
    for (int i = 0; i < NB; i++)
        zs[i][c] = zbase[(size_t)(nb + i) * C + c];
    __syncthreads();
    float b = bd[c];
    float acc[NB];
#pragma unroll
    for (int i = 0; i < NB; i++) acc[i] = b;
#pragma unroll 4
    for (int k = 0; k < C; k++) {
        float w = Wd[k * C + c];
#pragma unroll
        for (int i = 0; i < NB; i++)
            acc[i] = fmaf(zs[i][k], w, acc[i]);
    }
#pragma unroll
    for (int i = 0; i < NB; i++)
        out[(size_t)(nb + i) * C + c] = tanhf(acc[i]);
}

extern "C" void kernel_launch(void* const* d_in, const int* in_sizes, int n_in,
                              void* d_out, int out_size) {
    const float* x     = (const float*)d_in[0];
    const int*   ei    = (const int*)d_in[1];     // int32 (JAX x64 off)
    const float* W     = (const float*)d_in[2];
    const float* a_src = (const float*)d_in[3];
    const float* a_dst = (const float*)d_in[4];
    const float* b_gat = (const float*)d_in[5];
    const float* Wd    = (const float*)d_in[6];
    const float* bd    = (const float*)d_in[7];
    float* out  = (float*)d_out;
    float* zout = out + (size_t)N_NODES * C;

    int threads = 256;
    int eblocks = (E_TOT + threads - 1) / threads;

    k_zero<<<(N_NODES + 255) / 256, 256>>>();
    k_gemm1<<<N_NODES / NB, C>>>(x, W, a_src, a_dst);
    k_hist<<<eblocks, threads>>>(ei);
    k_scan1<<<NBLK, 1024>>>();
    k_scan2<<<1, 64>>>();
    k_scan3<<<NBLK, 1024>>>();
    k_fill<<<eblocks, threads>>>(ei);
    k_gather<<<N_NODES / 4, 128>>>(b_gat, zout);
    k_decode<<<N_NODES / NB, C>>>(Wd, bd, out);
}